// round 5
// baseline (speedup 1.0000x reference)
#include <cuda_runtime.h>

#define NS 512
#define HH 256
#define WW 256
#define HW (HH * WW)
#define NG 8
#define GS (NS / NG)
#define NB (HH * NG)        // 2048 blocks
#define NCB 1536            // combine blocks (x32 threads x float4)
#define EPSF 1e-6f
#define L2E 1.4426950408889634f
#define HPX (1.0f / 256.0f)

typedef unsigned long long u64;

__device__ float4 g_p0[NS];
__device__ float4 g_p1[NS];
__device__ float4 g_p2[NS];
__device__ float  g_part[NG][3 * HW];
__device__ float  g_red[NCB];
__device__ unsigned g_b1, g_b2, g_b3;   // zero-init; restored to 0 each call

__device__ __forceinline__ u64 ffma2(u64 a, u64 b, u64 c) {
    u64 d;
    asm("fma.rn.f32x2 %0, %1, %2, %3;" : "=l"(d) : "l"(a), "l"(b), "l"(c));
    return d;
}
__device__ __forceinline__ u64 pack2(float lo, float hi) {
    u64 d;
    asm("mov.b64 %0, {%1, %2};" : "=l"(d) : "f"(lo), "f"(hi));
    return d;
}
__device__ __forceinline__ void unpack2(u64 v, float& lo, float& hi) {
    asm("mov.b64 {%0, %1}, %2;" : "=f"(lo), "=f"(hi) : "l"(v));
}
__device__ __forceinline__ float ex2f(float x) {
    float r;
    asm("ex2.approx.ftz.f32 %0, %1;" : "=f"(r) : "f"(x));
    return r;
}
__device__ __forceinline__ void lds_v4f(unsigned addr, float4& v) {
    asm("ld.shared.v4.f32 {%0, %1, %2, %3}, [%4];"
        : "=f"(v.x), "=f"(v.y), "=f"(v.z), "=f"(v.w) : "r"(addr));
}
__device__ __forceinline__ void spin_until(volatile unsigned* p, unsigned tgt) {
    while (*p < tgt) __nanosleep(32);
}

__global__ void __launch_bounds__(32) fused_kernel(
    const float* __restrict__ canvas,
    const float* __restrict__ target,
    const float* __restrict__ offset,
    const float* __restrict__ sigma,
    const float* __restrict__ theta,
    const float* __restrict__ color,
    const float* __restrict__ alpha,
    float* __restrict__ out,
    int out_size)
{
    const int tid = threadIdx.x;
    const int bid = blockIdx.x;
    __shared__ float sh[GS * 8];   // 2 KB
    __shared__ int lf;

    // ---------------- Stage A: per-stroke params (blocks 0..15) ------------
    if (bid < 16) {
        const int n = bid * 32 + tid;
        const float ox = offset[2 * n + 0];
        const float oy = offset[2 * n + 1];
        const float sg0 = sigma[2 * n + 0];
        const float sg1 = sigma[2 * n + 1];
        const float th = theta[n];

        const float ratio = (float)WW / (float)HH;
        const float s0 = sg0 / ratio;
        float s, c;
        __sincosf(th, &s, &c);
        const float ia = __fdividef(0.5f, s0 * s0);
        const float ib = __fdividef(0.5f, sg1 * sg1);

        const float A = ia * c * c + ib * s * s;
        const float C = ia * s * s + ib * c * c;
        const float B = -2.0f * s * c * (ia + ib);

        const float Xm = (float)(WW - 1) / (float)WW;
        const float Ym = (float)(HH - 1) / (float)HH;
        const float x0d = -ox, x1d = Xm - ox;
        const float y0d = -oy, y1d = Ym - oy;

        float best = 3.4e38f, bdx = 0.0f, bdy = 0.0f;
        if (x0d <= 0.0f && x1d >= 0.0f && y0d <= 0.0f && y1d >= 0.0f) {
            best = 0.0f; bdx = 0.0f; bdy = 0.0f;
        }
        const float i2A = __fdividef(-0.5f, A);
        const float i2C = __fdividef(-0.5f, C);
        #pragma unroll
        for (int e = 0; e < 2; e++) {
            float ex = e ? x1d : x0d;
            float dyv = fminf(fmaxf(B * ex * i2C, y0d), y1d);
            float q = fmaf(A * ex, ex, fmaf(B * ex, dyv, C * dyv * dyv));
            if (q < best) { best = q; bdx = ex; bdy = dyv; }
        }
        #pragma unroll
        for (int e = 0; e < 2; e++) {
            float ey = e ? y1d : y0d;
            float dxv = fminf(fmaxf(B * ey * i2A, x0d), x1d);
            float q = fmaf(A * dxv, dxv, fmaf(B * dxv, ey, C * ey * ey));
            if (q < best) { best = q; bdx = dxv; bdy = ey; }
        }

        const float jx = floorf((bdx + ox) * (float)WW) - 1.0f;
        const float iy = floorf((bdy + oy) * (float)HH) - 1.0f;
        float mq = 3.4e38f;
        #pragma unroll
        for (int a2 = 0; a2 < 4; a2++) {
            float jj = fminf(fmaxf(jx + (float)a2, 0.0f), (float)(WW - 1));
            float dxv = jj * (1.0f / (float)WW) - ox;
            #pragma unroll
            for (int b2 = 0; b2 < 4; b2++) {
                float ii = fminf(fmaxf(iy + (float)b2, 0.0f), (float)(HH - 1));
                float dyv = ii * (1.0f / (float)HH) - oy;
                float q = fmaf(A * dxv, dxv, fmaf(B * dxv, dyv, C * dyv * dyv));
                mq = fminf(mq, q);
            }
        }

        const float maxpdf = __expf(-mq);
        const float scale = __fdividef(maxpdf, maxpdf + EPSF);
        const float al = alpha[n];
        const float w0 = al * color[3 * n + 0] * scale;
        const float w1 = al * color[3 * n + 1] * scale;
        const float w2 = al * color[3 * n + 2] * scale;

        const float a = -L2E * A;
        const float B0 = -2.0f * A * ox;
        const float C0 = A * ox * ox;
        const float C1 = -B * ox;
        const float K = exp2f(2.0f * a * HPX * HPX);

        g_p0[n] = make_float4(a, -L2E * B0, -L2E * B, oy);
        g_p1[n] = make_float4(L2E * (mq - C0), -L2E * C1, -L2E * C, w0);
        g_p2[n] = make_float4(w1, w2, K, 0.0f);

        __threadfence();
        __syncthreads();
        if (tid == 0) atomicAdd(&g_b1, 1u);
    }

    // ---------------- Barrier 1 -------------------------------------------
    if (tid == 0) spin_until(&g_b1, 16u);
    __syncthreads();

    // ---------------- Stage B: stroke accumulation ------------------------
    const int g = bid & (NG - 1);
    const int row = bid >> 3;
    const float rowy = (float)row * HPX;

    #pragma unroll
    for (int k = 0; k < 2; k++) {
        int sl = tid + 32 * k;
        int n = g * GS + sl;
        float4 p0 = g_p0[n];
        float4 p1 = g_p1[n];
        float4 p2 = g_p2[n];
        float dy = rowy - p0.w;
        float b = fmaf(p0.z, dy, p0.y);
        float cc = fmaf(fmaf(p1.z, dy, p1.y), dy, p1.x);
        float* d = &sh[sl * 8];
        d[0] = p0.x;
        d[1] = b;
        d[2] = cc;
        d[3] = b * HPX;
        d[4] = p2.z;
        d[5] = p1.w;
        d[6] = p2.x;
        d[7] = p2.y;
    }
    __syncthreads();

    const float x0 = (float)(tid * 8) * HPX;
    const float X1c = fmaf(2.0f * HPX, x0, HPX * HPX);

    u64 acc[3][4];
    #pragma unroll
    for (int ch = 0; ch < 3; ch++)
        #pragma unroll
        for (int k = 0; k < 4; k++) acc[ch][k] = 0ull;

    const unsigned sbase = (unsigned)__cvta_generic_to_shared(sh);

    #pragma unroll 2
    for (int sl = 0; sl < GS; sl++) {
        float4 q0, q1;
        lds_v4f(sbase + sl * 32, q0);
        lds_v4f(sbase + sl * 32 + 16, q1);
        const float a = q0.x, b = q0.y, cc = q0.z, bh = q0.w;
        const float K = q1.x;

        float m0 = fmaf(fmaf(a, x0, b), x0, cc);
        float d0 = fmaf(a, X1c, bh);
        float p0 = ex2f(m0);
        float t = ex2f(d0);
        float p1 = p0 * t; t *= K;
        float p2 = p1 * t; t *= K;
        float p3 = p2 * t; t *= K;
        float p4 = p3 * t; t *= K;
        float p5 = p4 * t; t *= K;
        float p6 = p5 * t; t *= K;
        float p7 = p6 * t;

        u64 pk0 = pack2(p0, p1);
        u64 pk1 = pack2(p2, p3);
        u64 pk2 = pack2(p4, p5);
        u64 pk3 = pack2(p6, p7);
        u64 ww0 = pack2(q1.y, q1.y);
        u64 ww1 = pack2(q1.z, q1.z);
        u64 ww2 = pack2(q1.w, q1.w);

        acc[0][0] = ffma2(pk0, ww0, acc[0][0]);
        acc[0][1] = ffma2(pk1, ww0, acc[0][1]);
        acc[0][2] = ffma2(pk2, ww0, acc[0][2]);
        acc[0][3] = ffma2(pk3, ww0, acc[0][3]);
        acc[1][0] = ffma2(pk0, ww1, acc[1][0]);
        acc[1][1] = ffma2(pk1, ww1, acc[1][1]);
        acc[1][2] = ffma2(pk2, ww1, acc[1][2]);
        acc[1][3] = ffma2(pk3, ww1, acc[1][3]);
        acc[2][0] = ffma2(pk0, ww2, acc[2][0]);
        acc[2][1] = ffma2(pk1, ww2, acc[2][1]);
        acc[2][2] = ffma2(pk2, ww2, acc[2][2]);
        acc[2][3] = ffma2(pk3, ww2, acc[2][3]);
    }

    const int base = row * WW + tid * 8;
    #pragma unroll
    for (int ch = 0; ch < 3; ch++) {
        float4* dst = (float4*)&g_part[g][ch * HW + base];
        float lo0, hi0, lo1, hi1;
        unpack2(acc[ch][0], lo0, hi0);
        unpack2(acc[ch][1], lo1, hi1);
        dst[0] = make_float4(lo0, hi0, lo1, hi1);
        unpack2(acc[ch][2], lo0, hi0);
        unpack2(acc[ch][3], lo1, hi1);
        dst[1] = make_float4(lo0, hi0, lo1, hi1);
    }

    __threadfence();
    __syncthreads();
    if (tid == 0) atomicAdd(&g_b2, 1u);

    // ---------------- Stage C: combine (blocks 0..NCB-1) ------------------
    if (bid >= NCB) return;

    if (tid == 0) spin_until(&g_b2, (unsigned)NB);
    __syncthreads();

    const int i = bid * 32 + tid;   // float4 index into 3*HW/4 = 49152
    float4 sum = ((const float4*)canvas)[i];
    #pragma unroll
    for (int gi = 0; gi < NG; gi++) {
        float4 p = ((const float4*)&g_part[gi][0])[i];
        sum.x += p.x; sum.y += p.y; sum.z += p.z; sum.w += p.w;
    }
    float4 o;
    o.x = __fdividef(1.0f, 1.0f + __expf(-sum.x));
    o.y = __fdividef(1.0f, 1.0f + __expf(-sum.y));
    o.z = __fdividef(1.0f, 1.0f + __expf(-sum.z));
    o.w = __fdividef(1.0f, 1.0f + __expf(-sum.w));
    ((float4*)out)[i] = o;

    float4 tg = ((const float4*)target)[i];
    float dx = o.x - tg.x, dy2 = o.y - tg.y, dz = o.z - tg.z, dw = o.w - tg.w;
    float sq = fmaf(dx, dx, fmaf(dy2, dy2, fmaf(dz, dz, dw * dw)));
    #pragma unroll
    for (int o2 = 16; o2 > 0; o2 >>= 1)
        sq += __shfl_down_sync(0xffffffffu, sq, o2);

    if (tid == 0) {
        g_red[bid] = sq;
        __threadfence();
        unsigned prev = atomicAdd(&g_b3, 1u);
        lf = (prev == (unsigned)(NCB - 1)) ? 1 : 0;
    }
    __syncthreads();

    // ---------------- Final loss (last combine block) ---------------------
    if (lf) {
        float pa = 0.f, pb = 0.f, pc = 0.f;
        #pragma unroll
        for (int k = 0; k < NCB / 32; k++)
            pa += g_red[tid + 32 * k];
        #pragma unroll
        for (int k = 0; k < NS / 32; k++) {
            int nn = tid + 32 * k;
            pb += fabsf(1.0f - __fdividef(sigma[2 * nn], sigma[2 * nn + 1]));
            pc += fabsf(alpha[nn]);
        }
        #pragma unroll
        for (int o2 = 16; o2 > 0; o2 >>= 1) {
            pa += __shfl_down_sync(0xffffffffu, pa, o2);
            pb += __shfl_down_sync(0xffffffffu, pb, o2);
            pc += __shfl_down_sync(0xffffffffu, pc, o2);
        }
        if (tid == 0) {
            float mse = pa / (float)(3 * HW);
            float sharp = pb * (0.001f / (float)NS);
            float transp = -pc * (0.001f / (float)NS);
            float psnr = -10.0f * log10f(mse + 1e-12f);
            float loss = mse + transp + sharp - psnr / 30.0f;
            if (out_size > 3 * HW) out[3 * HW] = loss;
            // restore counters for next graph replay (deterministic state)
            g_b1 = 0u; g_b2 = 0u; g_b3 = 0u;
        }
    }
}

extern "C" void kernel_launch(void* const* d_in, const int* in_sizes, int n_in,
                              void* d_out, int out_size)
{
    const float* canvas = (const float*)d_in[0];
    const float* target = (const float*)d_in[1];
    const float* offset = (const float*)d_in[2];
    const float* sigma  = (const float*)d_in[3];
    const float* theta  = (const float*)d_in[4];
    const float* color  = (const float*)d_in[5];
    const float* alpha  = (const float*)d_in[6];
    float* out = (float*)d_out;

    fused_kernel<<<NB, 32>>>(canvas, target, offset, sigma, theta, color,
                             alpha, out, out_size);
}

// round 6
// speedup vs baseline: 1.2666x; 1.2666x over previous
#include <cuda_runtime.h>

#define NS 512
#define HH 256
#define WW 256
#define HW (HH * WW)
#define NG 8
#define GS (NS / NG)
#define EPSF 1e-6f
#define L2E 1.4426950408889634f
#define HPX (1.0f / 256.0f)

typedef unsigned long long u64;

// g_p0[n] = {a, B0, B1, oy}
// g_p1[n] = {C0', C1, C2, w0}
// g_p2[n] = {w1, w2, K, K4}
__device__ float4 g_p0[NS];
__device__ float4 g_p1[NS];
__device__ float4 g_p2[NS];
__device__ float  g_part[NG][3 * HW];
__device__ float  g_red[192];
__device__ unsigned g_done;

__device__ __forceinline__ u64 ffma2(u64 a, u64 b, u64 c) {
    u64 d;
    asm("fma.rn.f32x2 %0, %1, %2, %3;" : "=l"(d) : "l"(a), "l"(b), "l"(c));
    return d;
}
__device__ __forceinline__ u64 fmul2(u64 a, u64 b) {
    u64 d;
    asm("mul.rn.f32x2 %0, %1, %2;" : "=l"(d) : "l"(a), "l"(b));
    return d;
}
__device__ __forceinline__ u64 pack2(float lo, float hi) {
    u64 d;
    asm("mov.b64 %0, {%1, %2};" : "=l"(d) : "f"(lo), "f"(hi));
    return d;
}
__device__ __forceinline__ void unpack2(u64 v, float& lo, float& hi) {
    asm("mov.b64 {%0, %1}, %2;" : "=f"(lo), "=f"(hi) : "l"(v));
}
__device__ __forceinline__ float ex2f(float x) {
    float r;
    asm("ex2.approx.ftz.f32 %0, %1;" : "=f"(r) : "f"(x));
    return r;
}
__device__ __forceinline__ void lds_v4f(unsigned addr, float4& v) {
    asm("ld.shared.v4.f32 {%0, %1, %2, %3}, [%4];"
        : "=f"(v.x), "=f"(v.y), "=f"(v.z), "=f"(v.w) : "r"(addr));
}
__device__ __forceinline__ void lds_v2u64(unsigned addr, u64& a, u64& b) {
    asm("ld.shared.v2.u64 {%0, %1}, [%2];" : "=l"(a), "=l"(b) : "r"(addr));
}

// ---------------------------------------------------------------------------
// Pass 1: one thread per stroke; closed-form rect min + 4x4 grid refinement.
// ---------------------------------------------------------------------------
__global__ void __launch_bounds__(256) pass1_kernel(
    const float* __restrict__ offset,
    const float* __restrict__ sigma,
    const float* __restrict__ theta,
    const float* __restrict__ color,
    const float* __restrict__ alpha)
{
    const int n = blockIdx.x * 256 + threadIdx.x;
    if (n == 0) g_done = 0;
    if (n >= NS) return;

    const float ox = offset[2 * n + 0];
    const float oy = offset[2 * n + 1];
    const float sg0 = sigma[2 * n + 0];
    const float sg1 = sigma[2 * n + 1];
    const float th = theta[n];

    const float ratio = (float)WW / (float)HH;
    const float s0 = sg0 / ratio;
    float s, c;
    __sincosf(th, &s, &c);
    const float ia = __fdividef(0.5f, s0 * s0);
    const float ib = __fdividef(0.5f, sg1 * sg1);

    const float A = ia * c * c + ib * s * s;
    const float C = ia * s * s + ib * c * c;
    const float B = -2.0f * s * c * (ia + ib);

    const float Xm = (float)(WW - 1) / (float)WW;
    const float Ym = (float)(HH - 1) / (float)HH;
    const float x0d = -ox, x1d = Xm - ox;
    const float y0d = -oy, y1d = Ym - oy;

    float best = 3.4e38f, bdx = 0.0f, bdy = 0.0f;
    if (x0d <= 0.0f && x1d >= 0.0f && y0d <= 0.0f && y1d >= 0.0f) {
        best = 0.0f; bdx = 0.0f; bdy = 0.0f;
    }
    const float i2A = __fdividef(-0.5f, A);
    const float i2C = __fdividef(-0.5f, C);
    #pragma unroll
    for (int e = 0; e < 2; e++) {
        float ex = e ? x1d : x0d;
        float dyv = fminf(fmaxf(B * ex * i2C, y0d), y1d);
        float q = fmaf(A * ex, ex, fmaf(B * ex, dyv, C * dyv * dyv));
        if (q < best) { best = q; bdx = ex; bdy = dyv; }
    }
    #pragma unroll
    for (int e = 0; e < 2; e++) {
        float ey = e ? y1d : y0d;
        float dxv = fminf(fmaxf(B * ey * i2A, x0d), x1d);
        float q = fmaf(A * dxv, dxv, fmaf(B * dxv, ey, C * ey * ey));
        if (q < best) { best = q; bdx = dxv; bdy = ey; }
    }

    const float jx = floorf((bdx + ox) * (float)WW) - 1.0f;
    const float iy = floorf((bdy + oy) * (float)HH) - 1.0f;
    float mq = 3.4e38f;
    #pragma unroll
    for (int a2 = 0; a2 < 4; a2++) {
        float jj = fminf(fmaxf(jx + (float)a2, 0.0f), (float)(WW - 1));
        float dxv = jj * (1.0f / (float)WW) - ox;
        #pragma unroll
        for (int b2 = 0; b2 < 4; b2++) {
            float ii = fminf(fmaxf(iy + (float)b2, 0.0f), (float)(HH - 1));
            float dyv = ii * (1.0f / (float)HH) - oy;
            float q = fmaf(A * dxv, dxv, fmaf(B * dxv, dyv, C * dyv * dyv));
            mq = fminf(mq, q);
        }
    }

    const float maxpdf = __expf(-mq);
    const float scale = __fdividef(maxpdf, maxpdf + EPSF);
    const float al = alpha[n];
    const float w0 = al * color[3 * n + 0] * scale;
    const float w1 = al * color[3 * n + 1] * scale;
    const float w2 = al * color[3 * n + 2] * scale;

    const float a = -L2E * A;
    const float B0 = -2.0f * A * ox;
    const float C0 = A * ox * ox;
    const float C1 = -B * ox;
    const float K = exp2f(2.0f * a * HPX * HPX);
    const float K4 = K * K * K * K;

    g_p0[n] = make_float4(a, -L2E * B0, -L2E * B, oy);
    g_p1[n] = make_float4(L2E * (mq - C0), -L2E * C1, -L2E * C, w0);
    g_p2[n] = make_float4(w1, w2, K, K4);
}

// ---------------------------------------------------------------------------
// Pass 2: 512 blocks x 128 threads. Block = (row, group-half); warp w handles
// group (half*4 + w). Thread owns 8 contiguous pixels. Per stroke:
// 3 LDS (incl. pre-duplicated 64-bit pairs), 2 EX2, packed geometric chain,
// 12 ffma2 accumulation. Writes per-group partials.
// Shared per stroke (16 floats): {a,b,cc,K} {K4,K4,w0,w0} {w1,w1,w2,w2} pad4
// ---------------------------------------------------------------------------
__global__ void __launch_bounds__(128) pass2_kernel()
{
    __shared__ float sh[256 * 16];   // 16 KB

    const int tid = threadIdx.x;
    const int lane = tid & 31;
    const int wid = tid >> 5;
    const int half = blockIdx.x & 1;
    const int row = blockIdx.x >> 1;
    const float rowy = (float)row * HPX;

    // preload + row-fold 256 strokes (2 per thread)
    #pragma unroll
    for (int k = tid; k < 256; k += 128) {
        int n = half * 256 + k;
        float4 p0 = g_p0[n];
        float4 p1 = g_p1[n];
        float4 p2 = g_p2[n];
        float dy = rowy - p0.w;
        float b = fmaf(p0.z, dy, p0.y);
        float cc = fmaf(fmaf(p1.z, dy, p1.y), dy, p1.x);
        float* d = &sh[k * 16];
        d[0] = p0.x;   // a
        d[1] = b;
        d[2] = cc;
        d[3] = p2.z;   // K
        d[4] = p2.w;   // K4
        d[5] = p2.w;
        d[6] = p1.w;   // w0
        d[7] = p1.w;
        d[8] = p2.x;   // w1
        d[9] = p2.x;
        d[10] = p2.y;  // w2
        d[11] = p2.y;
    }
    __syncthreads();

    const int g = half * 4 + wid;
    const float x0 = (float)(lane * 8) * HPX;
    const float X1c = fmaf(2.0f * HPX, x0, HPX * HPX);

    u64 acc[3][4];
    #pragma unroll
    for (int ch = 0; ch < 3; ch++)
        #pragma unroll
        for (int k = 0; k < 4; k++) acc[ch][k] = 0ull;

    const unsigned sbase = (unsigned)__cvta_generic_to_shared(sh) + wid * (GS * 64);

    #pragma unroll 4
    for (int sl = 0; sl < GS; sl++) {
        float4 q0;
        u64 K4v, ww0, ww1, ww2;
        lds_v4f(sbase + sl * 64, q0);
        lds_v2u64(sbase + sl * 64 + 16, K4v, ww0);
        lds_v2u64(sbase + sl * 64 + 32, ww1, ww2);

        const float a = q0.x, b = q0.y, cc = q0.z, K = q0.w;
        float m0 = fmaf(fmaf(a, x0, b), x0, cc);
        float d0 = fmaf(a, X1c, b * HPX);
        float p0 = ex2f(m0);
        float t0 = ex2f(d0);
        float p1 = p0 * t0;
        float t0sq = t0 * t0;
        float r0 = t0sq * K;
        float r1 = r0 * (K * K);

        u64 pk0 = pack2(p0, p1);
        u64 T = pack2(r0, r1);
        u64 pk1 = fmul2(pk0, T);
        u64 T2 = fmul2(T, K4v);
        u64 pk2 = fmul2(pk1, T2);
        u64 T3 = fmul2(T2, K4v);
        u64 pk3 = fmul2(pk2, T3);

        acc[0][0] = ffma2(pk0, ww0, acc[0][0]);
        acc[0][1] = ffma2(pk1, ww0, acc[0][1]);
        acc[0][2] = ffma2(pk2, ww0, acc[0][2]);
        acc[0][3] = ffma2(pk3, ww0, acc[0][3]);
        acc[1][0] = ffma2(pk0, ww1, acc[1][0]);
        acc[1][1] = ffma2(pk1, ww1, acc[1][1]);
        acc[1][2] = ffma2(pk2, ww1, acc[1][2]);
        acc[1][3] = ffma2(pk3, ww1, acc[1][3]);
        acc[2][0] = ffma2(pk0, ww2, acc[2][0]);
        acc[2][1] = ffma2(pk1, ww2, acc[2][1]);
        acc[2][2] = ffma2(pk2, ww2, acc[2][2]);
        acc[2][3] = ffma2(pk3, ww2, acc[2][3]);
    }

    const int base = row * WW + lane * 8;
    #pragma unroll
    for (int ch = 0; ch < 3; ch++) {
        float4* dst = (float4*)&g_part[g][ch * HW + base];
        float lo0, hi0, lo1, hi1;
        unpack2(acc[ch][0], lo0, hi0);
        unpack2(acc[ch][1], lo1, hi1);
        dst[0] = make_float4(lo0, hi0, lo1, hi1);
        unpack2(acc[ch][2], lo0, hi0);
        unpack2(acc[ch][3], lo1, hi1);
        dst[1] = make_float4(lo0, hi0, lo1, hi1);
    }
}

// ---------------------------------------------------------------------------
// Combine: 192 blocks x 256 threads, one float4 per thread.
// ---------------------------------------------------------------------------
__global__ void __launch_bounds__(256) combine_kernel(
    const float* __restrict__ canvas,
    const float* __restrict__ target,
    const float* __restrict__ sigma,
    const float* __restrict__ alpha,
    float* __restrict__ out,
    int out_size)
{
    __shared__ float ws[8];
    __shared__ int lastflag;

    const int tid = threadIdx.x;
    const int i = blockIdx.x * 256 + tid;

    float4 sum = ((const float4*)canvas)[i];
    #pragma unroll
    for (int gi = 0; gi < NG; gi++) {
        float4 p = ((const float4*)&g_part[gi][0])[i];
        sum.x += p.x; sum.y += p.y; sum.z += p.z; sum.w += p.w;
    }
    float4 o;
    o.x = __fdividef(1.0f, 1.0f + __expf(-sum.x));
    o.y = __fdividef(1.0f, 1.0f + __expf(-sum.y));
    o.z = __fdividef(1.0f, 1.0f + __expf(-sum.z));
    o.w = __fdividef(1.0f, 1.0f + __expf(-sum.w));
    ((float4*)out)[i] = o;

    float4 tg = ((const float4*)target)[i];
    float dx = o.x - tg.x, dy2 = o.y - tg.y, dz = o.z - tg.z, dw = o.w - tg.w;
    float sq = fmaf(dx, dx, fmaf(dy2, dy2, fmaf(dz, dz, dw * dw)));

    #pragma unroll
    for (int o2 = 16; o2 > 0; o2 >>= 1)
        sq += __shfl_down_sync(0xffffffffu, sq, o2);
    if ((tid & 31) == 0) ws[tid >> 5] = sq;
    __syncthreads();
    if (tid == 0) {
        float t2 = 0.f;
        #pragma unroll
        for (int k = 0; k < 8; k++) t2 += ws[k];
        g_red[blockIdx.x] = t2;
        __threadfence();
        unsigned prev = atomicAdd(&g_done, 1u);
        lastflag = (prev == 191u) ? 1 : 0;
    }
    __syncthreads();

    if (lastflag) {
        __shared__ float sa[256], sb[256], sc2[256];
        float pa = (tid < 192) ? g_red[tid] : 0.0f;
        float pb = 0.f, pc = 0.f;
        #pragma unroll
        for (int k = 0; k < 2; k++) {
            int nn = tid + 256 * k;
            pb += fabsf(1.0f - __fdividef(sigma[2 * nn], sigma[2 * nn + 1]));
            pc += fabsf(alpha[nn]);
        }
        sa[tid] = pa; sb[tid] = pb; sc2[tid] = pc;
        __syncthreads();
        for (int s2 = 128; s2 > 0; s2 >>= 1) {
            if (tid < s2) {
                sa[tid] += sa[tid + s2];
                sb[tid] += sb[tid + s2];
                sc2[tid] += sc2[tid + s2];
            }
            __syncthreads();
        }
        if (tid == 0) {
            float mse = sa[0] / (float)(3 * HW);
            float sharp = sb[0] * (0.001f / (float)NS);
            float transp = -sc2[0] * (0.001f / (float)NS);
            float psnr = -10.0f * log10f(mse + 1e-12f);
            float loss = mse + transp + sharp - psnr / 30.0f;
            if (out_size > 3 * HW) out[3 * HW] = loss;
        }
    }
}

// ---------------------------------------------------------------------------
extern "C" void kernel_launch(void* const* d_in, const int* in_sizes, int n_in,
                              void* d_out, int out_size)
{
    const float* canvas = (const float*)d_in[0];
    const float* target = (const float*)d_in[1];
    const float* offset = (const float*)d_in[2];
    const float* sigma  = (const float*)d_in[3];
    const float* theta  = (const float*)d_in[4];
    const float* color  = (const float*)d_in[5];
    const float* alpha  = (const float*)d_in[6];
    float* out = (float*)d_out;

    pass1_kernel<<<2, 256>>>(offset, sigma, theta, color, alpha);
    pass2_kernel<<<512, 128>>>();
    combine_kernel<<<192, 256>>>(canvas, target, sigma, alpha, out, out_size);
}

// round 7
// speedup vs baseline: 1.2820x; 1.0122x over previous
#include <cuda_runtime.h>

#define NS 512
#define HH 256
#define WW 256
#define HW (HH * WW)
#define NG 16
#define GS (NS / NG)        // 32 strokes per group
#define EPSF 1e-6f
#define L2E 1.4426950408889634f
#define HPX (1.0f / 256.0f)

typedef unsigned long long u64;

// g_p0[n] = {a, B0, B1, oy}
// g_p1[n] = {C0', C1, C2, w0}
// g_p2[n] = {w1, w2, K, K4}
__device__ float4 g_p0[NS];
__device__ float4 g_p1[NS];
__device__ float4 g_p2[NS];
__device__ float  g_part[NG][3 * HW];
__device__ float  g_red[192];
__device__ unsigned g_done;

__device__ __forceinline__ u64 ffma2(u64 a, u64 b, u64 c) {
    u64 d;
    asm("fma.rn.f32x2 %0, %1, %2, %3;" : "=l"(d) : "l"(a), "l"(b), "l"(c));
    return d;
}
__device__ __forceinline__ u64 fmul2(u64 a, u64 b) {
    u64 d;
    asm("mul.rn.f32x2 %0, %1, %2;" : "=l"(d) : "l"(a), "l"(b));
    return d;
}
__device__ __forceinline__ u64 pack2(float lo, float hi) {
    u64 d;
    asm("mov.b64 %0, {%1, %2};" : "=l"(d) : "f"(lo), "f"(hi));
    return d;
}
__device__ __forceinline__ void unpack2(u64 v, float& lo, float& hi) {
    asm("mov.b64 {%0, %1}, %2;" : "=f"(lo), "=f"(hi) : "l"(v));
}
__device__ __forceinline__ float ex2f(float x) {
    float r;
    asm("ex2.approx.ftz.f32 %0, %1;" : "=f"(r) : "f"(x));
    return r;
}
__device__ __forceinline__ void lds_v4f(unsigned addr, float4& v) {
    asm("ld.shared.v4.f32 {%0, %1, %2, %3}, [%4];"
        : "=f"(v.x), "=f"(v.y), "=f"(v.z), "=f"(v.w) : "r"(addr));
}
__device__ __forceinline__ void lds_v2u64(unsigned addr, u64& a, u64& b) {
    asm("ld.shared.v2.u64 {%0, %1}, [%2];" : "=l"(a), "=l"(b) : "r"(addr));
}

// ---------------------------------------------------------------------------
// Pass 1: one thread per stroke; closed-form rect min + 4x4 grid refinement.
// ---------------------------------------------------------------------------
__global__ void __launch_bounds__(256) pass1_kernel(
    const float* __restrict__ offset,
    const float* __restrict__ sigma,
    const float* __restrict__ theta,
    const float* __restrict__ color,
    const float* __restrict__ alpha)
{
    const int n = blockIdx.x * 256 + threadIdx.x;
    if (n == 0) g_done = 0;
    if (n >= NS) return;

    const float ox = offset[2 * n + 0];
    const float oy = offset[2 * n + 1];
    const float sg0 = sigma[2 * n + 0];
    const float sg1 = sigma[2 * n + 1];
    const float th = theta[n];

    const float ratio = (float)WW / (float)HH;
    const float s0 = sg0 / ratio;
    float s, c;
    __sincosf(th, &s, &c);
    const float ia = __fdividef(0.5f, s0 * s0);
    const float ib = __fdividef(0.5f, sg1 * sg1);

    const float A = ia * c * c + ib * s * s;
    const float C = ia * s * s + ib * c * c;
    const float B = -2.0f * s * c * (ia + ib);

    const float Xm = (float)(WW - 1) / (float)WW;
    const float Ym = (float)(HH - 1) / (float)HH;
    const float x0d = -ox, x1d = Xm - ox;
    const float y0d = -oy, y1d = Ym - oy;

    float best = 3.4e38f, bdx = 0.0f, bdy = 0.0f;
    if (x0d <= 0.0f && x1d >= 0.0f && y0d <= 0.0f && y1d >= 0.0f) {
        best = 0.0f; bdx = 0.0f; bdy = 0.0f;
    }
    const float i2A = __fdividef(-0.5f, A);
    const float i2C = __fdividef(-0.5f, C);
    #pragma unroll
    for (int e = 0; e < 2; e++) {
        float ex = e ? x1d : x0d;
        float dyv = fminf(fmaxf(B * ex * i2C, y0d), y1d);
        float q = fmaf(A * ex, ex, fmaf(B * ex, dyv, C * dyv * dyv));
        if (q < best) { best = q; bdx = ex; bdy = dyv; }
    }
    #pragma unroll
    for (int e = 0; e < 2; e++) {
        float ey = e ? y1d : y0d;
        float dxv = fminf(fmaxf(B * ey * i2A, x0d), x1d);
        float q = fmaf(A * dxv, dxv, fmaf(B * dxv, ey, C * ey * ey));
        if (q < best) { best = q; bdx = dxv; bdy = ey; }
    }

    const float jx = floorf((bdx + ox) * (float)WW) - 1.0f;
    const float iy = floorf((bdy + oy) * (float)HH) - 1.0f;
    float mq = 3.4e38f;
    #pragma unroll
    for (int a2 = 0; a2 < 4; a2++) {
        float jj = fminf(fmaxf(jx + (float)a2, 0.0f), (float)(WW - 1));
        float dxv = jj * (1.0f / (float)WW) - ox;
        #pragma unroll
        for (int b2 = 0; b2 < 4; b2++) {
            float ii = fminf(fmaxf(iy + (float)b2, 0.0f), (float)(HH - 1));
            float dyv = ii * (1.0f / (float)HH) - oy;
            float q = fmaf(A * dxv, dxv, fmaf(B * dxv, dyv, C * dyv * dyv));
            mq = fminf(mq, q);
        }
    }

    const float maxpdf = __expf(-mq);
    const float scale = __fdividef(maxpdf, maxpdf + EPSF);
    const float al = alpha[n];
    const float w0 = al * color[3 * n + 0] * scale;
    const float w1 = al * color[3 * n + 1] * scale;
    const float w2 = al * color[3 * n + 2] * scale;

    const float a = -L2E * A;
    const float B0 = -2.0f * A * ox;
    const float C0 = A * ox * ox;
    const float C1 = -B * ox;
    const float K = exp2f(2.0f * a * HPX * HPX);
    const float K4 = K * K * K * K;

    g_p0[n] = make_float4(a, -L2E * B0, -L2E * B, oy);
    g_p1[n] = make_float4(L2E * (mq - C0), -L2E * C1, -L2E * C, w0);
    g_p2[n] = make_float4(w1, w2, K, K4);
}

// ---------------------------------------------------------------------------
// Pass 2: 1024 blocks x 128 threads. block = (row, stroke-quarter). The 4
// warps each own one 32-stroke group; each lane owns 8 contiguous pixels.
// Per stroke: 3 LDS, 2 EX2, packed geometric chain, 12 ffma2 accumulation.
// Shared per stroke (16 floats): {a,b,cc,K} {K4,K4,w0,w0} {w1,w1,w2,w2} {bh,..}
// ---------------------------------------------------------------------------
__global__ void __launch_bounds__(128) pass2_kernel()
{
    __shared__ float sh[128 * 16];   // 8 KB

    const int tid = threadIdx.x;
    const int lane = tid & 31;
    const int wid = tid >> 5;
    const int quad = blockIdx.x & 3;
    const int row = blockIdx.x >> 2;
    const float rowy = (float)row * HPX;

    // preload + row-fold 128 strokes (1 per thread)
    {
        int n = quad * 128 + tid;
        float4 p0 = g_p0[n];
        float4 p1 = g_p1[n];
        float4 p2 = g_p2[n];
        float dy = rowy - p0.w;
        float b = fmaf(p0.z, dy, p0.y);
        float cc = fmaf(fmaf(p1.z, dy, p1.y), dy, p1.x);
        float* d = &sh[tid * 16];
        d[0] = p0.x;       // a
        d[1] = b;
        d[2] = cc;
        d[3] = p2.z;       // K
        d[4] = p2.w;       // K4 (duplicated pair)
        d[5] = p2.w;
        d[6] = p1.w;       // w0 pair
        d[7] = p1.w;
        d[8] = p2.x;       // w1 pair
        d[9] = p2.x;
        d[10] = p2.y;      // w2 pair
        d[11] = p2.y;
        d[12] = b * HPX;   // bh
    }
    __syncthreads();

    const int g = quad * 4 + wid;
    const float x0 = (float)(lane * 8) * HPX;
    const float X1c = fmaf(2.0f * HPX, x0, HPX * HPX);

    u64 acc[3][4];
    #pragma unroll
    for (int ch = 0; ch < 3; ch++)
        #pragma unroll
        for (int k = 0; k < 4; k++) acc[ch][k] = 0ull;

    const unsigned sbase = (unsigned)__cvta_generic_to_shared(sh) + wid * (GS * 64);

    #pragma unroll 4
    for (int sl = 0; sl < GS; sl++) {
        float4 q0;
        u64 K4v, ww0, ww1, ww2;
        float bh;
        lds_v4f(sbase + sl * 64, q0);
        lds_v2u64(sbase + sl * 64 + 16, K4v, ww0);
        lds_v2u64(sbase + sl * 64 + 32, ww1, ww2);
        asm("ld.shared.f32 %0, [%1];" : "=f"(bh) : "r"(sbase + sl * 64 + 48));

        const float a = q0.x, b = q0.y, cc = q0.z, K = q0.w;
        float m0 = fmaf(fmaf(a, x0, b), x0, cc);
        float d0 = fmaf(a, X1c, bh);
        float p0 = ex2f(m0);
        float t0 = ex2f(d0);
        float p1 = p0 * t0;
        float t0sq = t0 * t0;
        float r0 = t0sq * K;
        float r1 = r0 * (K * K);

        u64 pk0 = pack2(p0, p1);
        u64 T = pack2(r0, r1);
        u64 pk1 = fmul2(pk0, T);
        u64 T2 = fmul2(T, K4v);
        u64 pk2 = fmul2(pk1, T2);
        u64 T3 = fmul2(T2, K4v);
        u64 pk3 = fmul2(pk2, T3);

        acc[0][0] = ffma2(pk0, ww0, acc[0][0]);
        acc[0][1] = ffma2(pk1, ww0, acc[0][1]);
        acc[0][2] = ffma2(pk2, ww0, acc[0][2]);
        acc[0][3] = ffma2(pk3, ww0, acc[0][3]);
        acc[1][0] = ffma2(pk0, ww1, acc[1][0]);
        acc[1][1] = ffma2(pk1, ww1, acc[1][1]);
        acc[1][2] = ffma2(pk2, ww1, acc[1][2]);
        acc[1][3] = ffma2(pk3, ww1, acc[1][3]);
        acc[2][0] = ffma2(pk0, ww2, acc[2][0]);
        acc[2][1] = ffma2(pk1, ww2, acc[2][1]);
        acc[2][2] = ffma2(pk2, ww2, acc[2][2]);
        acc[2][3] = ffma2(pk3, ww2, acc[2][3]);
    }

    const int base = row * WW + lane * 8;
    #pragma unroll
    for (int ch = 0; ch < 3; ch++) {
        float4* dst = (float4*)&g_part[g][ch * HW + base];
        float lo0, hi0, lo1, hi1;
        unpack2(acc[ch][0], lo0, hi0);
        unpack2(acc[ch][1], lo1, hi1);
        dst[0] = make_float4(lo0, hi0, lo1, hi1);
        unpack2(acc[ch][2], lo0, hi0);
        unpack2(acc[ch][3], lo1, hi1);
        dst[1] = make_float4(lo0, hi0, lo1, hi1);
    }
}

// ---------------------------------------------------------------------------
// Combine: 192 blocks x 256 threads, one float4 per thread.
// ---------------------------------------------------------------------------
__global__ void __launch_bounds__(256) combine_kernel(
    const float* __restrict__ canvas,
    const float* __restrict__ target,
    const float* __restrict__ sigma,
    const float* __restrict__ alpha,
    float* __restrict__ out,
    int out_size)
{
    __shared__ float ws[8];
    __shared__ int lastflag;

    const int tid = threadIdx.x;
    const int i = blockIdx.x * 256 + tid;

    float4 sum = ((const float4*)canvas)[i];
    #pragma unroll
    for (int gi = 0; gi < NG; gi++) {
        float4 p = ((const float4*)&g_part[gi][0])[i];
        sum.x += p.x; sum.y += p.y; sum.z += p.z; sum.w += p.w;
    }
    float4 o;
    o.x = __fdividef(1.0f, 1.0f + __expf(-sum.x));
    o.y = __fdividef(1.0f, 1.0f + __expf(-sum.y));
    o.z = __fdividef(1.0f, 1.0f + __expf(-sum.z));
    o.w = __fdividef(1.0f, 1.0f + __expf(-sum.w));
    ((float4*)out)[i] = o;

    float4 tg = ((const float4*)target)[i];
    float dx = o.x - tg.x, dy2 = o.y - tg.y, dz = o.z - tg.z, dw = o.w - tg.w;
    float sq = fmaf(dx, dx, fmaf(dy2, dy2, fmaf(dz, dz, dw * dw)));

    #pragma unroll
    for (int o2 = 16; o2 > 0; o2 >>= 1)
        sq += __shfl_down_sync(0xffffffffu, sq, o2);
    if ((tid & 31) == 0) ws[tid >> 5] = sq;
    __syncthreads();
    if (tid == 0) {
        float t2 = 0.f;
        #pragma unroll
        for (int k = 0; k < 8; k++) t2 += ws[k];
        g_red[blockIdx.x] = t2;
        __threadfence();
        unsigned prev = atomicAdd(&g_done, 1u);
        lastflag = (prev == 191u) ? 1 : 0;
    }
    __syncthreads();

    if (lastflag) {
        __shared__ float sa[256], sb[256], sc2[256];
        float pa = (tid < 192) ? g_red[tid] : 0.0f;
        float pb = 0.f, pc = 0.f;
        #pragma unroll
        for (int k = 0; k < 2; k++) {
            int nn = tid + 256 * k;
            pb += fabsf(1.0f - __fdividef(sigma[2 * nn], sigma[2 * nn + 1]));
            pc += fabsf(alpha[nn]);
        }
        sa[tid] = pa; sb[tid] = pb; sc2[tid] = pc;
        __syncthreads();
        for (int s2 = 128; s2 > 0; s2 >>= 1) {
            if (tid < s2) {
                sa[tid] += sa[tid + s2];
                sb[tid] += sb[tid + s2];
                sc2[tid] += sc2[tid + s2];
            }
            __syncthreads();
        }
        if (tid == 0) {
            float mse = sa[0] / (float)(3 * HW);
            float sharp = sb[0] * (0.001f / (float)NS);
            float transp = -sc2[0] * (0.001f / (float)NS);
            float psnr = -10.0f * log10f(mse + 1e-12f);
            float loss = mse + transp + sharp - psnr / 30.0f;
            if (out_size > 3 * HW) out[3 * HW] = loss;
        }
    }
}

// ---------------------------------------------------------------------------
extern "C" void kernel_launch(void* const* d_in, const int* in_sizes, int n_in,
                              void* d_out, int out_size)
{
    const float* canvas = (const float*)d_in[0];
    const float* target = (const float*)d_in[1];
    const float* offset = (const float*)d_in[2];
    const float* sigma  = (const float*)d_in[3];
    const float* theta  = (const float*)d_in[4];
    const float* color  = (const float*)d_in[5];
    const float* alpha  = (const float*)d_in[6];
    float* out = (float*)d_out;

    pass1_kernel<<<2, 256>>>(offset, sigma, theta, color, alpha);
    pass2_kernel<<<1024, 128>>>();
    combine_kernel<<<192, 256>>>(canvas, target, sigma, alpha, out, out_size);
}

// round 8
// speedup vs baseline: 1.4206x; 1.1081x over previous
#include <cuda_runtime.h>

#define NS 512
#define HH 256
#define WW 256
#define HW (HH * WW)
#define NG 16
#define GS (NS / NG)        // 32 strokes per group (one warp per group)
#define EPSF 1e-6f
#define L2E 1.4426950408889634f
#define HPX (1.0f / 256.0f)

typedef unsigned long long u64;

__device__ float  g_part[NG][3 * HW];
__device__ float  g_red[192];
__device__ unsigned g_done;    // zero-init; last combine block restores to 0

__device__ __forceinline__ u64 ffma2(u64 a, u64 b, u64 c) {
    u64 d;
    asm("fma.rn.f32x2 %0, %1, %2, %3;" : "=l"(d) : "l"(a), "l"(b), "l"(c));
    return d;
}
__device__ __forceinline__ u64 fmul2(u64 a, u64 b) {
    u64 d;
    asm("mul.rn.f32x2 %0, %1, %2;" : "=l"(d) : "l"(a), "l"(b));
    return d;
}
__device__ __forceinline__ u64 pack2(float lo, float hi) {
    u64 d;
    asm("mov.b64 %0, {%1, %2};" : "=l"(d) : "f"(lo), "f"(hi));
    return d;
}
__device__ __forceinline__ void unpack2(u64 v, float& lo, float& hi) {
    asm("mov.b64 {%0, %1}, %2;" : "=f"(lo), "=f"(hi) : "l"(v));
}
__device__ __forceinline__ float ex2f(float x) {
    float r;
    asm("ex2.approx.ftz.f32 %0, %1;" : "=f"(r) : "f"(x));
    return r;
}
__device__ __forceinline__ void lds_v4f(unsigned addr, float4& v) {
    asm("ld.shared.v4.f32 {%0, %1, %2, %3}, [%4];"
        : "=f"(v.x), "=f"(v.y), "=f"(v.z), "=f"(v.w) : "r"(addr));
}
__device__ __forceinline__ void lds_v2u64(unsigned addr, u64& a, u64& b) {
    asm("ld.shared.v2.u64 {%0, %1}, [%2];" : "=l"(a), "=l"(b) : "r"(addr));
}

// ---------------------------------------------------------------------------
// Pass 2 (now first kernel): 1024 blocks x 128 threads.
// block = (row, stroke-quarter). Preload: each thread computes FULL stroke
// params INLINE (closed-form rect min + 4x4 grid refinement) for one stroke
// of the block's 128, then row-folds into shared. Main loop unchanged:
// per stroke 3 LDS, 2 EX2, packed geometric chain, 12 ffma2.
// ---------------------------------------------------------------------------
__global__ void __launch_bounds__(128) pass2_kernel(
    const float* __restrict__ offset,
    const float* __restrict__ sigma,
    const float* __restrict__ theta,
    const float* __restrict__ color,
    const float* __restrict__ alpha)
{
    __shared__ float sh[128 * 16];   // 8 KB

    const int tid = threadIdx.x;
    const int lane = tid & 31;
    const int wid = tid >> 5;
    const int quad = blockIdx.x & 3;
    const int row = blockIdx.x >> 2;
    const float rowy = (float)row * HPX;

    // ---- inline stroke-param computation (one stroke per thread) ----------
    {
        const int n = quad * 128 + tid;
        const float ox = offset[2 * n + 0];
        const float oy = offset[2 * n + 1];
        const float sg0 = sigma[2 * n + 0];
        const float sg1 = sigma[2 * n + 1];
        const float th = theta[n];

        const float ratio = (float)WW / (float)HH;
        const float s0 = sg0 / ratio;
        float s, c;
        __sincosf(th, &s, &c);
        const float ia = __fdividef(0.5f, s0 * s0);
        const float ib = __fdividef(0.5f, sg1 * sg1);

        const float A = ia * c * c + ib * s * s;
        const float C = ia * s * s + ib * c * c;
        const float B = -2.0f * s * c * (ia + ib);

        const float Xm = (float)(WW - 1) / (float)WW;
        const float Ym = (float)(HH - 1) / (float)HH;
        const float x0d = -ox, x1d = Xm - ox;
        const float y0d = -oy, y1d = Ym - oy;

        float best = 3.4e38f, bdx = 0.0f, bdy = 0.0f;
        if (x0d <= 0.0f && x1d >= 0.0f && y0d <= 0.0f && y1d >= 0.0f) {
            best = 0.0f; bdx = 0.0f; bdy = 0.0f;
        }
        const float i2A = __fdividef(-0.5f, A);
        const float i2C = __fdividef(-0.5f, C);
        #pragma unroll
        for (int e = 0; e < 2; e++) {
            float ex = e ? x1d : x0d;
            float dyv = fminf(fmaxf(B * ex * i2C, y0d), y1d);
            float q = fmaf(A * ex, ex, fmaf(B * ex, dyv, C * dyv * dyv));
            if (q < best) { best = q; bdx = ex; bdy = dyv; }
        }
        #pragma unroll
        for (int e = 0; e < 2; e++) {
            float ey = e ? y1d : y0d;
            float dxv = fminf(fmaxf(B * ey * i2A, x0d), x1d);
            float q = fmaf(A * dxv, dxv, fmaf(B * dxv, ey, C * ey * ey));
            if (q < best) { best = q; bdx = dxv; bdy = ey; }
        }

        const float jx = floorf((bdx + ox) * (float)WW) - 1.0f;
        const float iy = floorf((bdy + oy) * (float)HH) - 1.0f;
        float mq = 3.4e38f;
        #pragma unroll
        for (int a2 = 0; a2 < 4; a2++) {
            float jj = fminf(fmaxf(jx + (float)a2, 0.0f), (float)(WW - 1));
            float dxv = jj * (1.0f / (float)WW) - ox;
            #pragma unroll
            for (int b2 = 0; b2 < 4; b2++) {
                float ii = fminf(fmaxf(iy + (float)b2, 0.0f), (float)(HH - 1));
                float dyv = ii * (1.0f / (float)HH) - oy;
                float q = fmaf(A * dxv, dxv, fmaf(B * dxv, dyv, C * dyv * dyv));
                mq = fminf(mq, q);
            }
        }

        const float maxpdf = __expf(-mq);
        const float scale = __fdividef(maxpdf, maxpdf + EPSF);
        const float al = alpha[n];
        const float w0 = al * color[3 * n + 0] * scale;
        const float w1 = al * color[3 * n + 1] * scale;
        const float w2 = al * color[3 * n + 2] * scale;

        // log2-scaled polynomial coefficients
        const float aL  = -L2E * A;
        const float bL0 = -L2E * (-2.0f * A * ox);
        const float bL1 = -L2E * B;
        const float cL0 = L2E * (mq - A * ox * ox);
        const float cL1 = -L2E * (-B * ox);
        const float cL2 = -L2E * C;
        const float K = exp2f(2.0f * aL * HPX * HPX);
        const float K4 = ((K * K) * (K * K));

        // row-fold for THIS block's row
        const float dy = rowy - oy;
        const float b = fmaf(bL1, dy, bL0);
        const float cc = fmaf(fmaf(cL2, dy, cL1), dy, cL0);

        float* d = &sh[tid * 16];
        d[0] = aL;
        d[1] = b;
        d[2] = cc;
        d[3] = K;
        d[4] = K4;  d[5] = K4;     // duplicated pair
        d[6] = w0;  d[7] = w0;
        d[8] = w1;  d[9] = w1;
        d[10] = w2; d[11] = w2;
        d[12] = b * HPX;           // bh
    }
    __syncthreads();

    const int g = quad * 4 + wid;
    const float x0 = (float)(lane * 8) * HPX;
    const float X1c = fmaf(2.0f * HPX, x0, HPX * HPX);

    u64 acc[3][4];
    #pragma unroll
    for (int ch = 0; ch < 3; ch++)
        #pragma unroll
        for (int k = 0; k < 4; k++) acc[ch][k] = 0ull;

    const unsigned sbase = (unsigned)__cvta_generic_to_shared(sh) + wid * (GS * 64);

    #pragma unroll 4
    for (int sl = 0; sl < GS; sl++) {
        float4 q0;
        u64 K4v, ww0, ww1, ww2;
        float bh;
        lds_v4f(sbase + sl * 64, q0);
        lds_v2u64(sbase + sl * 64 + 16, K4v, ww0);
        lds_v2u64(sbase + sl * 64 + 32, ww1, ww2);
        asm("ld.shared.f32 %0, [%1];" : "=f"(bh) : "r"(sbase + sl * 64 + 48));

        const float a = q0.x, b = q0.y, cc = q0.z, K = q0.w;
        float m0 = fmaf(fmaf(a, x0, b), x0, cc);
        float d0 = fmaf(a, X1c, bh);
        float p0 = ex2f(m0);
        float t0 = ex2f(d0);
        float p1 = p0 * t0;
        float t0sq = t0 * t0;
        float r0 = t0sq * K;
        float r1 = r0 * (K * K);

        u64 pk0 = pack2(p0, p1);
        u64 T = pack2(r0, r1);
        u64 pk1 = fmul2(pk0, T);
        u64 T2 = fmul2(T, K4v);
        u64 pk2 = fmul2(pk1, T2);
        u64 T3 = fmul2(T2, K4v);
        u64 pk3 = fmul2(pk2, T3);

        acc[0][0] = ffma2(pk0, ww0, acc[0][0]);
        acc[0][1] = ffma2(pk1, ww0, acc[0][1]);
        acc[0][2] = ffma2(pk2, ww0, acc[0][2]);
        acc[0][3] = ffma2(pk3, ww0, acc[0][3]);
        acc[1][0] = ffma2(pk0, ww1, acc[1][0]);
        acc[1][1] = ffma2(pk1, ww1, acc[1][1]);
        acc[1][2] = ffma2(pk2, ww1, acc[1][2]);
        acc[1][3] = ffma2(pk3, ww1, acc[1][3]);
        acc[2][0] = ffma2(pk0, ww2, acc[2][0]);
        acc[2][1] = ffma2(pk1, ww2, acc[2][1]);
        acc[2][2] = ffma2(pk2, ww2, acc[2][2]);
        acc[2][3] = ffma2(pk3, ww2, acc[2][3]);
    }

    const int base = row * WW + lane * 8;
    #pragma unroll
    for (int ch = 0; ch < 3; ch++) {
        float4* dst = (float4*)&g_part[g][ch * HW + base];
        float lo0, hi0, lo1, hi1;
        unpack2(acc[ch][0], lo0, hi0);
        unpack2(acc[ch][1], lo1, hi1);
        dst[0] = make_float4(lo0, hi0, lo1, hi1);
        unpack2(acc[ch][2], lo0, hi0);
        unpack2(acc[ch][3], lo1, hi1);
        dst[1] = make_float4(lo0, hi0, lo1, hi1);
    }
}

// ---------------------------------------------------------------------------
// Combine: 192 blocks x 256 threads, one float4 per thread.
// ---------------------------------------------------------------------------
__global__ void __launch_bounds__(256) combine_kernel(
    const float* __restrict__ canvas,
    const float* __restrict__ target,
    const float* __restrict__ sigma,
    const float* __restrict__ alpha,
    float* __restrict__ out,
    int out_size)
{
    __shared__ float ws[8];
    __shared__ int lastflag;

    const int tid = threadIdx.x;
    const int i = blockIdx.x * 256 + tid;

    float4 sum = ((const float4*)canvas)[i];
    #pragma unroll
    for (int gi = 0; gi < NG; gi++) {
        float4 p = ((const float4*)&g_part[gi][0])[i];
        sum.x += p.x; sum.y += p.y; sum.z += p.z; sum.w += p.w;
    }
    float4 o;
    o.x = __fdividef(1.0f, 1.0f + __expf(-sum.x));
    o.y = __fdividef(1.0f, 1.0f + __expf(-sum.y));
    o.z = __fdividef(1.0f, 1.0f + __expf(-sum.z));
    o.w = __fdividef(1.0f, 1.0f + __expf(-sum.w));
    ((float4*)out)[i] = o;

    float4 tg = ((const float4*)target)[i];
    float dx = o.x - tg.x, dy2 = o.y - tg.y, dz = o.z - tg.z, dw = o.w - tg.w;
    float sq = fmaf(dx, dx, fmaf(dy2, dy2, fmaf(dz, dz, dw * dw)));

    #pragma unroll
    for (int o2 = 16; o2 > 0; o2 >>= 1)
        sq += __shfl_down_sync(0xffffffffu, sq, o2);
    if ((tid & 31) == 0) ws[tid >> 5] = sq;
    __syncthreads();
    if (tid == 0) {
        float t2 = 0.f;
        #pragma unroll
        for (int k = 0; k < 8; k++) t2 += ws[k];
        g_red[blockIdx.x] = t2;
        __threadfence();
        unsigned prev = atomicAdd(&g_done, 1u);
        lastflag = (prev == 191u) ? 1 : 0;
    }
    __syncthreads();

    if (lastflag) {
        __shared__ float sa[256], sb[256], sc2[256];
        float pa = (tid < 192) ? g_red[tid] : 0.0f;
        float pb = 0.f, pc = 0.f;
        #pragma unroll
        for (int k = 0; k < 2; k++) {
            int nn = tid + 256 * k;
            pb += fabsf(1.0f - __fdividef(sigma[2 * nn], sigma[2 * nn + 1]));
            pc += fabsf(alpha[nn]);
        }
        sa[tid] = pa; sb[tid] = pb; sc2[tid] = pc;
        __syncthreads();
        for (int s2 = 128; s2 > 0; s2 >>= 1) {
            if (tid < s2) {
                sa[tid] += sa[tid + s2];
                sb[tid] += sb[tid + s2];
                sc2[tid] += sc2[tid + s2];
            }
            __syncthreads();
        }
        if (tid == 0) {
            float mse = sa[0] / (float)(3 * HW);
            float sharp = sb[0] * (0.001f / (float)NS);
            float transp = -sc2[0] * (0.001f / (float)NS);
            float psnr = -10.0f * log10f(mse + 1e-12f);
            float loss = mse + transp + sharp - psnr / 30.0f;
            if (out_size > 3 * HW) out[3 * HW] = loss;
            g_done = 0u;   // restore state for next graph replay
        }
    }
}

// ---------------------------------------------------------------------------
extern "C" void kernel_launch(void* const* d_in, const int* in_sizes, int n_in,
                              void* d_out, int out_size)
{
    const float* canvas = (const float*)d_in[0];
    const float* target = (const float*)d_in[1];
    const float* offset = (const float*)d_in[2];
    const float* sigma  = (const float*)d_in[3];
    const float* theta  = (const float*)d_in[4];
    const float* color  = (const float*)d_in[5];
    const float* alpha  = (const float*)d_in[6];
    float* out = (float*)d_out;

    pass2_kernel<<<1024, 128>>>(offset, sigma, theta, color, alpha);
    combine_kernel<<<192, 256>>>(canvas, target, sigma, alpha, out, out_size);
}